// round 8
// baseline (speedup 1.0000x reference)
#include <cuda_runtime.h>
#include <math.h>

// Fused: binarized-conv(3x3,Cin=1,Cout=32,SAME) + global-avg-pool + dense(32->10) + softmax.
// pooling commutes with conv: p[b,co] = conv_b[co] + (1/4096)*sum_k sign(w[k,co])*S[b,k],
// S[b,k] = 9 shifted sums from {total, row0, row63, col0, col63, 4 corners}.
// 2 images per CTA (256 CTAs): all 8 float4 loads issued up front (MLP=8); warp 2
// stages weights to smem; warps 2-7 bar.arrive+exit; warps 0/1 bar.sync and run the
// two epilogues in parallel, smem/register-only.

#define B_TOTAL 512
#define HW 4096
#define NCO 32
#define NCLS 10

__global__ __launch_bounds__(256, 2)
void fused_bnn_kernel(const float* __restrict__ x,
                      const float* __restrict__ conv_w,   // [9,32]
                      const float* __restrict__ conv_b,   // [32]
                      const float* __restrict__ dense_w,  // [32,10]
                      const float* __restrict__ dense_b,  // [10]
                      float* __restrict__ out)            // [512,10]
{
    __shared__ float warpsum[2][5][8];
    __shared__ float corn[2][4];          // per image: x[0,0], x[0,63], x[63,0], x[63,63]
    __shared__ float s_cw[9 * NCO];
    __shared__ float s_cb[NCO];
    __shared__ float s_dw[NCO * NCLS];
    __shared__ float s_db[NCLS];

    const int tid  = threadIdx.x;         // 256
    const int lane = tid & 31;
    const int wid  = tid >> 5;
    const unsigned FULL = 0xffffffffu;

    const float4* imgA = reinterpret_cast<const float4*>(x + (size_t)(2 * blockIdx.x) * HW);
    const float4* imgB = imgA + (HW / 4);

    // ---- all image loads issued back-to-back (MLP = 8) ----
    float4 a0 = imgA[tid];       float4 a1 = imgA[tid + 256];
    float4 a2 = imgA[tid + 512]; float4 a3 = imgA[tid + 768];
    float4 b0 = imgB[tid];       float4 b1 = imgB[tid + 256];
    float4 b2 = imgB[tid + 512]; float4 b3 = imgB[tid + 768];

    // ---- warp 2: stage weights to smem (overlaps DRAM waits) ----
    if (wid == 2) {
        #pragma unroll
        for (int k = 0; k < 9; k++) s_cw[k * NCO + lane] = conv_w[k * NCO + lane];
        s_cb[lane] = conv_b[lane];
        #pragma unroll
        for (int n = 0; n < NCLS; n++) s_dw[lane * NCLS + n] = dense_w[lane * NCLS + n];
        if (lane < NCLS) s_db[lane] = dense_b[lane];
    }

    // ---- per-thread stats, both images ----
    // float4 f covers floats [4f,4f+4); row=f>>4; col0 iff (f&15)==0 (.x); col63 iff (f&15)==15 (.w)
    float as0 = (a0.x + a0.y) + (a0.z + a0.w);
    float as1 = (a1.x + a1.y) + (a1.z + a1.w);
    float as2 = (a2.x + a2.y) + (a2.z + a2.w);
    float as3 = (a3.x + a3.y) + (a3.z + a3.w);
    float bs0 = (b0.x + b0.y) + (b0.z + b0.w);
    float bs1 = (b1.x + b1.y) + (b1.z + b1.w);
    float bs2 = (b2.x + b2.y) + (b2.z + b2.w);
    float bs3 = (b3.x + b3.y) + (b3.z + b3.w);

    const bool isC0  = ((tid & 15) == 0);
    const bool isC63 = ((tid & 15) == 15);

    float TA   = (as0 + as1) + (as2 + as3);
    float R0A  = (tid < 16)   ? as0 : 0.0f;
    float R63A = (tid >= 240) ? as3 : 0.0f;
    float C0A  = isC0  ? (a0.x + a1.x) + (a2.x + a3.x) : 0.0f;
    float C63A = isC63 ? (a0.w + a1.w) + (a2.w + a3.w) : 0.0f;

    float TB   = (bs0 + bs1) + (bs2 + bs3);
    float R0B  = (tid < 16)   ? bs0 : 0.0f;
    float R63B = (tid >= 240) ? bs3 : 0.0f;
    float C0B  = isC0  ? (b0.x + b1.x) + (b2.x + b3.x) : 0.0f;
    float C63B = isC63 ? (b0.w + b1.w) + (b2.w + b3.w) : 0.0f;

    if (tid == 0)   { corn[0][0] = a0.x; corn[1][0] = b0.x; }   // x[0,0]
    if (tid == 15)  { corn[0][1] = a0.w; corn[1][1] = b0.w; }   // x[0,63]
    if (tid == 240) { corn[0][2] = a3.x; corn[1][2] = b3.x; }   // x[63,0]
    if (tid == 255) { corn[0][3] = a3.w; corn[1][3] = b3.w; }   // x[63,63]

    #pragma unroll
    for (int off = 16; off > 0; off >>= 1) {
        TA   += __shfl_down_sync(FULL, TA,   off);
        R0A  += __shfl_down_sync(FULL, R0A,  off);
        R63A += __shfl_down_sync(FULL, R63A, off);
        C0A  += __shfl_down_sync(FULL, C0A,  off);
        C63A += __shfl_down_sync(FULL, C63A, off);
        TB   += __shfl_down_sync(FULL, TB,   off);
        R0B  += __shfl_down_sync(FULL, R0B,  off);
        R63B += __shfl_down_sync(FULL, R63B, off);
        C0B  += __shfl_down_sync(FULL, C0B,  off);
        C63B += __shfl_down_sync(FULL, C63B, off);
    }
    if (lane == 0) {
        warpsum[0][0][wid] = TA;  warpsum[0][1][wid] = R0A;  warpsum[0][2][wid] = R63A;
        warpsum[0][3][wid] = C0A; warpsum[0][4][wid] = C63A;
        warpsum[1][0][wid] = TB;  warpsum[1][1][wid] = R0B;  warpsum[1][2][wid] = R63B;
        warpsum[1][3][wid] = C0B; warpsum[1][4][wid] = C63B;
    }

    // ---- split barrier: producers arrive & retire, consumers (warps 0,1) sync ----
    if (wid >= 2) {
        asm volatile("bar.arrive 0, 256;" ::: "memory");
        return;
    }
    asm volatile("bar.sync 0, 256;" ::: "memory");

    const int img = wid;   // warp 0 -> image A, warp 1 -> image B

    float stat = 0.0f;
    if (lane < 5) {
        #pragma unroll
        for (int i = 0; i < 8; i++) stat += warpsum[img][lane][i];
    }
    float t   = __shfl_sync(FULL, stat, 0);
    float r0  = __shfl_sync(FULL, stat, 1);
    float r63 = __shfl_sync(FULL, stat, 2);
    float c0  = __shfl_sync(FULL, stat, 3);
    float c63 = __shfl_sync(FULL, stat, 4);
    float x00 = corn[img][0], x0e = corn[img][1], xe0 = corn[img][2], xee = corn[img][3];

    float S0 = t - r63 - c63 + xee, S1 = t - r63, S2 = t - r63 - c0 + xe0;
    float S3 = t - c63,             S4 = t,       S5 = t - c0;
    float S6 = t - r0  - c63 + x0e, S7 = t - r0,  S8 = t - r0  - c0 + x00;

    // Channel co = lane: p = conv_b + (1/4096) * sum_k sign(conv_w[k,co]) * S[k]
    float acc = (s_cw[0*NCO+lane] >= 0.f ? S0 : -S0)
              + (s_cw[1*NCO+lane] >= 0.f ? S1 : -S1)
              + (s_cw[2*NCO+lane] >= 0.f ? S2 : -S2)
              + (s_cw[3*NCO+lane] >= 0.f ? S3 : -S3)
              + (s_cw[4*NCO+lane] >= 0.f ? S4 : -S4)
              + (s_cw[5*NCO+lane] >= 0.f ? S5 : -S5)
              + (s_cw[6*NCO+lane] >= 0.f ? S6 : -S6)
              + (s_cw[7*NCO+lane] >= 0.f ? S7 : -S7)
              + (s_cw[8*NCO+lane] >= 0.f ? S8 : -S8);
    float p = s_cb[lane] + acc * (1.0f / (float)HW);

    // Transposed dense: lane=co contributes p * dense_w[co][n] into 10 accumulators,
    // 10 parallel butterflies -> every lane holds all logits.
    float lg[NCLS];
    #pragma unroll
    for (int n = 0; n < NCLS; n++) lg[n] = p * s_dw[lane * NCLS + n];
    #pragma unroll
    for (int off = 16; off > 0; off >>= 1) {
        #pragma unroll
        for (int n = 0; n < NCLS; n++) lg[n] += __shfl_xor_sync(FULL, lg[n], off);
    }
    #pragma unroll
    for (int n = 0; n < NCLS; n++) lg[n] += s_db[n];

    // Softmax in registers.
    float m = lg[0];
    #pragma unroll
    for (int n = 1; n < NCLS; n++) m = fmaxf(m, lg[n]);
    float e[NCLS], d = 0.0f;
    #pragma unroll
    for (int n = 0; n < NCLS; n++) { e[n] = __expf(lg[n] - m); d += e[n]; }
    float inv = __fdividef(1.0f, d);

    if (lane < NCLS) out[(2 * blockIdx.x + img) * NCLS + lane] = e[lane] * inv;
}

extern "C" void kernel_launch(void* const* d_in, const int* in_sizes, int n_in,
                              void* d_out, int out_size) {
    const float* x       = (const float*)d_in[0];
    const float* conv_w  = (const float*)d_in[1];
    const float* conv_b  = (const float*)d_in[2];
    const float* dense_w = (const float*)d_in[3];
    const float* dense_b = (const float*)d_in[4];
    float* out = (float*)d_out;
    (void)in_sizes; (void)n_in; (void)out_size;

    fused_bnn_kernel<<<B_TOTAL / 2, 256>>>(x, conv_w, conv_b, dense_w, dense_b, out);
}